// round 7
// baseline (speedup 1.0000x reference)
#include <cuda_runtime.h>
#include <cuda_bf16.h>
#include <cstdint>

// StackLSTM T=256, B=64, H=1024, L=2 — Round 7.
// mma.sync bf16 3-term split (a_hi@Whi + a_hi@Wlo + a_lo@Whi), fp32 accum.
// R7: PERSISTENT kernel (1 launch, 512 layer-steps in-kernel, software grid
// barrier). Weight (A) pipeline never drains: next step's A-chunks prefetch
// before epilogue+barrier; only activation (B) loads wait for the barrier.
// 3 stages, continuous stage rotation (step+i)%3, uniform wait_group<=1.

#define Tt 256
#define Bb 64
#define Hh 1024
#define BH (Bb * Hh)                 // 65536
#define M4H 4096
#define KK 2048
#define WPL (2ULL * M4H * KK)        // bf16 elems per layer (hi+lo planes)
#define STAGE 24576                  // A 8KB (hi+lo) + B 16KB (hi+lo)
#define NSTAGE 3
#define GSZ (NSTAGE * STAGE)         // 73728 per group
#define GB_BYTES (8 * 32 * 66 * 4)   // 67584 epilogue exchange buffer
#define SMEM_TOTAL (2 * GSZ + GB_BYTES)  // 215040
#define NCTA 128
#define NSTEP (2 * Tt)               // 512

// ---------------- persistent device state ----------------
__device__ __nv_bfloat16 g_xhi[Tt * BH];
__device__ __nv_bfloat16 g_xlo[Tt * BH];
__device__ __nv_bfloat16 g_W[2 * WPL];       // [layer][hl][4096 perm rows][2048]
__device__ float         g_bsum[2 * M4H];
__device__ __nv_bfloat16 g_Hhi[4 * BH];      // [layer*2+parity][BH]
__device__ __nv_bfloat16 g_Hlo[4 * BH];
__device__ float         g_C[2 * BH];
__device__ float         g_Hf[BH];           // top-layer final hidden (fp32)
__device__ unsigned int  g_barcnt;
__device__ unsigned int  g_bargen;

// ---------------- helpers ----------------
__device__ __forceinline__ uint32_t smem_u32(const void* p) {
    uint32_t a;
    asm("{ .reg .u64 t; cvta.to.shared.u64 t, %1; cvt.u32.u64 %0, t; }"
        : "=r"(a) : "l"(p));
    return a;
}
__device__ __forceinline__ void cp16(uint32_t d, const void* g) {
    asm volatile("cp.async.cg.shared.global [%0], [%1], 16;"
                 :: "r"(d), "l"(g) : "memory");
}
#define CP_COMMIT() asm volatile("cp.async.commit_group;" ::: "memory")
#define CP_WAIT1()  asm volatile("cp.async.wait_group 1;" ::: "memory")
#define CP_WAIT0()  asm volatile("cp.async.wait_group 0;" ::: "memory")

#define LDSM4(r, addr) \
    asm volatile("ldmatrix.sync.aligned.m8n8.x4.shared.b16 {%0,%1,%2,%3}, [%4];" \
        : "=r"((r)[0]), "=r"((r)[1]), "=r"((r)[2]), "=r"((r)[3]) : "r"(addr))

#define HMMA(d, a0, a1, a2, a3, b0, b1) \
    asm volatile("mma.sync.aligned.m16n8k16.row.col.f32.bf16.bf16.f32 " \
        "{%0,%1,%2,%3},{%4,%5,%6,%7},{%8,%9},{%0,%1,%2,%3};" \
        : "+f"((d)[0]), "+f"((d)[1]), "+f"((d)[2]), "+f"((d)[3]) \
        : "r"(a0), "r"(a1), "r"(a2), "r"(a3), "r"(b0), "r"(b1))

__device__ __forceinline__ void gbar(int grp) {
    if (grp == 0) asm volatile("bar.sync 1, 256;" ::: "memory");
    else          asm volatile("bar.sync 2, 256;" ::: "memory");
}

__device__ __forceinline__ void grid_bar(unsigned int target) {
    __threadfence();
    __syncthreads();                 // all threads' writes fenced before arrive
    if (threadIdx.x == 0) {
        if (atomicAdd(&g_barcnt, 1u) == NCTA - 1) {
            g_barcnt = 0;            // safe: all others already arrived
            __threadfence();
            atomicExch(&g_bargen, target);
        } else {
            while (atomicAdd(&g_bargen, 0u) < target) { }
        }
    }
    __syncthreads();
    __threadfence();                 // acquire: see other CTAs' h stores
}

__device__ __forceinline__ float sigm(float x) { return 1.0f / (1.0f + __expf(-x)); }
__device__ __forceinline__ float tanh_(float x) {
    float ax = fabsf(x);
    float e  = __expf(-2.0f * ax);
    return copysignf((1.0f - e) / (1.0f + e), x);
}

// ---------------- prep kernels ----------------
__global__ void split_x_kernel(const float* __restrict__ x, int n) {
    for (int i = blockIdx.x * blockDim.x + threadIdx.x; i < n;
         i += gridDim.x * blockDim.x) {
        float v = x[i];
        __nv_bfloat16 hi = __float2bfloat16(v);
        g_xhi[i] = hi;
        g_xlo[i] = __float2bfloat16(v - __bfloat162float(hi));
    }
}

__global__ void init_state_kernel(const float* __restrict__ h0,
                                  const float* __restrict__ c0,
                                  const float* __restrict__ bih,
                                  const float* __restrict__ bhh) {
    int t0 = blockIdx.x * blockDim.x + threadIdx.x;
    if (t0 == 0) { g_barcnt = 0; g_bargen = 0; }
    for (int idx = t0; idx < 2 * BH; idx += gridDim.x * blockDim.x) {
        int l = idx / BH, r = idx % BH;
        float hv = h0[idx];
        __nv_bfloat16 hi = __float2bfloat16(hv);
        g_Hhi[(l * 2 + 0) * BH + r] = hi;
        g_Hlo[(l * 2 + 0) * BH + r] = __float2bfloat16(hv - __bfloat162float(hi));
        g_C[idx] = c0[idx];
    }
    for (int idx = t0; idx < 2 * M4H; idx += gridDim.x * blockDim.x)
        g_bsum[idx] = bih[idx] + bhh[idx];
}

// g_W[l][hl][p][k]: permuted row p: blk=p>>5, lcl=p&31, gate=lcl>>3, jl=lcl&7,
// j=blk*8+jl, source row = gate*1024+j. k<1024 -> Wih, else Whh.
__global__ void prep_w_kernel(const float* __restrict__ Wih,
                              const float* __restrict__ Whh) {
    const long long per = (long long)M4H * KK;
    const long long n   = 2 * 2 * per;
    for (long long idx = blockIdx.x * (long long)blockDim.x + threadIdx.x; idx < n;
         idx += (long long)gridDim.x * blockDim.x) {
        int  l  = (int)(idx / (2 * per));
        long long r1 = idx % (2 * per);
        int  hl = (int)(r1 / per);
        long long r2 = r1 % per;
        int  p  = (int)(r2 / KK), k = (int)(r2 % KK);
        int  blk = p >> 5, lcl = p & 31;
        int  gate = lcl >> 3, jl = lcl & 7;
        int  j = blk * 8 + jl;
        int  srow = gate * 1024 + j;
        float w = (k < 1024)
                ? Wih[(size_t)l * M4H * Hh + (size_t)srow * Hh + k]
                : Whh[(size_t)l * M4H * Hh + (size_t)srow * Hh + (k - 1024)];
        __nv_bfloat16 hi = __float2bfloat16(w);
        g_W[idx] = hl ? __float2bfloat16(w - __bfloat162float(hi)) : hi;
    }
}

// ---------------- persistent LSTM kernel ----------------
// grid = 128 CTAs (M=32 gate-rows each, fixed for all steps), block = 512.
// 2 K-split groups x 8 warps; warp: sub=k16 slot, half=N32 half, tile M32xN32.
__global__ void __launch_bounds__(512, 1) lstm_persist(
    const __nv_bfloat16* __restrict__ W,
    const float*         __restrict__ bsum,
    const __nv_bfloat16* __restrict__ xhi,
    const __nv_bfloat16* __restrict__ xlo,
    __nv_bfloat16* __restrict__ Hhi,
    __nv_bfloat16* __restrict__ Hlo,
    float* __restrict__ C,
    float* __restrict__ Hf)
{
    extern __shared__ char smem[];
    const int tid  = threadIdx.x;
    const int grp  = tid >> 8;
    const int gtid = tid & 255;
    const int gwid = gtid >> 5, lane = tid & 31;
    const int blk  = blockIdx.x;
    const int sub  = gwid >> 1;
    const int half = gwid & 1;
    const uint32_t sb = smem_u32(smem) + grp * GSZ;
    float* gb = (float*)(smem + 2 * GSZ);   // [8][32][66] dedicated

    // fragment addressing (swizzled smem, 128B rows)
    const int rA  = lane & 15;
    const int rB  = (lane & 7) + ((lane >> 4) << 3);
    const uint32_t qa = 2 * sub + (lane >> 4);
    const uint32_t qb = 2 * sub + ((lane >> 3) & 1);
    const uint32_t aOff = rA * 128 + (((qa ^ (rA & 7))) << 4);
    const uint32_t bOff = (half * 32 + rB) * 128 + (((qb ^ (rB & 7))) << 4);

    const __nv_bfloat16* Wcta = W + (size_t)(blk * 32) * KK + (size_t)grp * 1024;

    // A loader: weights of layer base Wb, chunk ci (koff = ci*64), stage st
    auto loadA = [&](const __nv_bfloat16* Wb, int ci, int st) {
        const uint32_t stA = sb + st * STAGE;
        const int koff = ci * 64;
#pragma unroll
        for (int i = 0; i < 2; i++) {
            int u = gtid + i * 256;
            int hl = u >> 8, rem = u & 255, row = rem >> 3, q = rem & 7;
            const __nv_bfloat16* s = Wb + (size_t)hl * ((size_t)M4H * KK)
                                   + (size_t)row * KK + koff + q * 8;
            cp16(stA + hl * 4096 + row * 128 + ((q ^ (row & 7)) << 4), s);
        }
    };
    // B loader: activations hi/lo, chunk ci, stage st
    auto loadB = [&](const __nv_bfloat16* bh, const __nv_bfloat16* bl,
                     int ci, int st) {
        const uint32_t stB = sb + st * STAGE + 8192;
        const int koff = ci * 64;
#pragma unroll
        for (int i = 0; i < 4; i++) {
            int u = gtid + i * 256;
            int hl = u >> 9, rem = u & 511, row = rem >> 3, q = rem & 7;
            const __nv_bfloat16* s =
                (hl ? bl : bh) + (size_t)row * 1024 + koff + q * 8;
            cp16(stB + hl * 8192 + row * 128 + ((q ^ (row & 7)) << 4), s);
        }
    };
    // B sources for a given step, for THIS group
    auto bsrc = [&](int s, const __nv_bfloat16*& bh, const __nv_bfloat16*& bl) {
        const int ly = s & 1, tt = s >> 1, pp = tt & 1;
        if (grp == 0) {
            if (ly == 0) { bh = xhi + (size_t)tt * BH; bl = xlo + (size_t)tt * BH; }
            else {
                bh = Hhi + (size_t)(pp ^ 1) * BH;   // layer0 fresh hidden
                bl = Hlo + (size_t)(pp ^ 1) * BH;
            }
        } else {
            const int ix = ly * 2 + pp;             // this layer's prev hidden
            bh = Hhi + (size_t)ix * BH;
            bl = Hlo + (size_t)ix * BH;
        }
    };

    for (int step = 0; step < NSTEP; ++step) {
        const int ly = step & 1, t = step >> 1, p = t & 1;
        const __nv_bfloat16* Wst = Wcta + (size_t)ly * WPL;
        const __nv_bfloat16* Wnx = Wcta + (size_t)((step + 1) & 1) * WPL;
        const __nv_bfloat16 *bhs, *bls;
        bsrc(step, bhs, bls);

        // head: chunks 0,1. step 0: full loads; else A was prefetched at the
        // tail of the previous step, only B (post-barrier) goes in now.
        const int st0 = step % 3, st1 = (step + 1) % 3;
        if (step == 0) {
            loadA(Wst, 0, st0); loadB(bhs, bls, 0, st0); CP_COMMIT();
            loadA(Wst, 1, st1); loadB(bhs, bls, 1, st1); CP_COMMIT();
        } else {
            loadB(bhs, bls, 0, st0); CP_COMMIT();
            loadB(bhs, bls, 1, st1); CP_COMMIT();
        }

        float acc[8][4];
#pragma unroll
        for (int i = 0; i < 8; i++)
#pragma unroll
            for (int r = 0; r < 4; r++) acc[i][r] = 0.f;

        for (int i = 0; i < 16; ++i) {
            if (step == NSTEP - 1 && i == 15) CP_WAIT0();
            else                              CP_WAIT1();
            gbar(grp);   // group done with the stage being overwritten below
            if (i <= 13) {
                const int st = (step + i + 2) % 3;
                loadA(Wst, i + 2, st);
                loadB(bhs, bls, i + 2, st);
                CP_COMMIT();
            } else if (step < NSTEP - 1) {
                // prefetch next step's A (weights) through epilogue + barrier
                loadA(Wnx, i - 14, (step + 1 + (i - 14)) % 3);
                CP_COMMIT();
            }

            const uint32_t stA = sb + ((step + i) % 3) * STAGE;
            const uint32_t stB = stA + 8192;
            uint32_t ah0[4], ah1[4], al0[4], al1[4];
            uint32_t bh0[4], bh1[4], bl0[4], bl1[4];
            LDSM4(ah0, stA + aOff);
            LDSM4(ah1, stA + aOff + 2048);
            LDSM4(al0, stA + aOff + 4096);
            LDSM4(al1, stA + aOff + 4096 + 2048);
            LDSM4(bh0, stB + bOff);
            LDSM4(bh1, stB + bOff + 2048);
            LDSM4(bl0, stB + bOff + 8192);
            LDSM4(bl1, stB + bOff + 8192 + 2048);
#pragma unroll
            for (int tm = 0; tm < 3; tm++) {
                const uint32_t* a0 = (tm == 2) ? al0 : ah0;
                const uint32_t* a1 = (tm == 2) ? al1 : ah1;
                const uint32_t* b0 = (tm == 1) ? bl0 : bh0;
                const uint32_t* b1 = (tm == 1) ? bl1 : bh1;
                HMMA(acc[0], a0[0], a0[1], a0[2], a0[3], b0[0], b0[1]);
                HMMA(acc[1], a0[0], a0[1], a0[2], a0[3], b0[2], b0[3]);
                HMMA(acc[2], a0[0], a0[1], a0[2], a0[3], b1[0], b1[1]);
                HMMA(acc[3], a0[0], a0[1], a0[2], a0[3], b1[2], b1[3]);
                HMMA(acc[4], a1[0], a1[1], a1[2], a1[3], b0[0], b0[1]);
                HMMA(acc[5], a1[0], a1[1], a1[2], a1[3], b0[2], b0[3]);
                HMMA(acc[6], a1[0], a1[1], a1[2], a1[3], b1[0], b1[1]);
                HMMA(acc[7], a1[0], a1[1], a1[2], a1[3], b1[2], b1[3]);
            }
        }

        // ---------------- epilogue: 8 partials -> fused LSTM cell ----------
        {
            float* myb = gb + (grp * 4 + sub) * (32 * 66);
            const int mrow = lane >> 2;
            const int ncol = 2 * (lane & 3);
#pragma unroll
            for (int i = 0; i < 8; i++) {
                const int mt = i >> 2, nt = (i >> 1) & 1, u = i & 1;
                const int m = mt * 16 + mrow;
                const int n = half * 32 + nt * 16 + u * 8 + ncol;
                *(float2*)&myb[m * 66 + n]       = make_float2(acc[i][0], acc[i][1]);
                *(float2*)&myb[(m + 8) * 66 + n] = make_float2(acc[i][2], acc[i][3]);
            }
        }
        __syncthreads();
        {
            const int jl = tid & 7;
            const int b  = tid >> 3;
            const int j  = blk * 8 + jl;
            const float* bsl = bsum + ly * M4H;
            float gsum[4];
#pragma unroll
            for (int g = 0; g < 4; g++) {
                float s = 0.f;
#pragma unroll
                for (int pp2 = 0; pp2 < 8; pp2++)
                    s += gb[(pp2 * 32 + g * 8 + jl) * 66 + b];
                gsum[g] = s;
            }
            float gi = gsum[0] + bsl[j];
            float gf = gsum[1] + bsl[1024 + j];
            float gg = gsum[2] + bsl[2048 + j];
            float go = gsum[3] + bsl[3072 + j];
            float* Cl = C + (size_t)ly * BH;
            float cn = sigm(gf) * Cl[b * Hh + j] + sigm(gi) * tanh_(gg);
            Cl[b * Hh + j] = cn;
            float hn = sigm(go) * tanh_(cn);
            const size_t ox = (size_t)(ly * 2 + (p ^ 1)) * BH + b * Hh + j;
            __nv_bfloat16 hi = __float2bfloat16(hn);
            Hhi[ox] = hi;
            Hlo[ox] = __float2bfloat16(hn - __bfloat162float(hi));
            if (step == NSTEP - 1) Hf[b * Hh + j] = hn;
        }

        if (step < NSTEP - 1) grid_bar((unsigned)(step + 1));
    }
}

// ---------------- host launcher ----------------
extern "C" void kernel_launch(void* const* d_in, const int* in_sizes, int n_in,
                              void* d_out, int out_size) {
    const float* x_seq = (const float*)d_in[0];
    const float* h0    = (const float*)d_in[1];
    const float* c0    = (const float*)d_in[2];
    const float* Wih   = (const float*)d_in[3];
    const float* Whh   = (const float*)d_in[4];
    const float* bih   = (const float*)d_in[5];
    const float* bhh   = (const float*)d_in[6];

    cudaFuncSetAttribute(lstm_persist,
                         cudaFuncAttributeMaxDynamicSharedMemorySize, SMEM_TOTAL);

    void *p_xhi, *p_xlo, *p_w, *p_bs, *p_hhi, *p_hlo, *p_c, *p_hf;
    cudaGetSymbolAddress(&p_xhi, g_xhi);
    cudaGetSymbolAddress(&p_xlo, g_xlo);
    cudaGetSymbolAddress(&p_w,   g_W);
    cudaGetSymbolAddress(&p_bs,  g_bsum);
    cudaGetSymbolAddress(&p_hhi, g_Hhi);
    cudaGetSymbolAddress(&p_hlo, g_Hlo);
    cudaGetSymbolAddress(&p_c,   g_C);
    cudaGetSymbolAddress(&p_hf,  g_Hf);

    split_x_kernel<<<8192, 256>>>(x_seq, Tt * BH);
    init_state_kernel<<<512, 256>>>(h0, c0, bih, bhh);
    prep_w_kernel<<<8192, 256>>>(Wih, Whh);

    lstm_persist<<<NCTA, 512, SMEM_TOTAL>>>(
        (const __nv_bfloat16*)p_w, (const float*)p_bs,
        (const __nv_bfloat16*)p_xhi, (const __nv_bfloat16*)p_xlo,
        (__nv_bfloat16*)p_hhi, (__nv_bfloat16*)p_hlo,
        (float*)p_c, (float*)p_hf);

    cudaMemcpyAsync(d_out, p_hf, (size_t)BH * sizeof(float),
                    cudaMemcpyDeviceToDevice);
}